// round 5
// baseline (speedup 1.0000x reference)
#include <cuda_runtime.h>
#include <cuda_bf16.h>
#include <cstdint>

// LSTM decoder: B=1024, H=128, O=7, T=512.
// gates = h @ (W_ih+W_hh)^T + (b_ih+b_hh)
// 128 blocks x 256 threads (2 warps/SMSP). Thread pair (t, t+128) owns hidden
// unit u = t&127: low half computes gates i,f; high half computes g (SMEM) and
// o (L2 stream). Gate exchange via SMEM; elementwise split rows 0-3 / 4-7.
// Inner products in packed fp32x2 (fma.rn.f32x2).

#define B_TOTAL   1024
#define HID       128
#define GATES     512
#define T_STEPS   512
#define OUT_DIM   7
#define ROWS      8
#define NBLOCKS   (B_TOTAL / ROWS)   // 128
#define TPB       256

__device__ float4 g_W[32 * GATES];        // [k4][g] combined transposed weights, 256 KB
__device__ float  g_bias[GATES];

// ---------- helpers ----------
__device__ __forceinline__ void ffma2(unsigned long long& d,
                                      unsigned long long a,
                                      unsigned long long b) {
    asm("fma.rn.f32x2 %0, %1, %2, %0;" : "+l"(d) : "l"(a), "l"(b));
}
__device__ __forceinline__ float pairsum(unsigned long long v) {
    float a, b;
    asm("mov.b64 {%0, %1}, %2;" : "=f"(a), "=f"(b) : "l"(v));
    return a + b;
}
__device__ __forceinline__ float sigf(float x) {
    return __fdividef(1.0f, 1.0f + __expf(-x));
}
__device__ __forceinline__ float tanh_fast(float x) {
    return __fdividef(2.0f, 1.0f + __expf(-2.0f * x)) - 1.0f;
}

// ---------- prep ----------
__global__ void prep_kernel(const float* __restrict__ Wih,
                            const float* __restrict__ Whh,
                            const float* __restrict__ bih,
                            const float* __restrict__ bhh) {
    int idx = blockIdx.x * blockDim.x + threadIdx.x;
    if (idx < 32 * GATES) {
        int g  = idx & (GATES - 1);
        int k4 = idx >> 9;
        int base = g * HID + k4 * 4;
        float4 v;
        v.x = Wih[base + 0] + Whh[base + 0];
        v.y = Wih[base + 1] + Whh[base + 1];
        v.z = Wih[base + 2] + Whh[base + 2];
        v.w = Wih[base + 3] + Whh[base + 3];
        g_W[k4 * GATES + g] = v;
    }
    if (idx < GATES) g_bias[idx] = bih[idx] + bhh[idx];
}

// ---------- SMEM layout (floats) ----------
#define SW_F4       (32 * 384)            // 12288 float4 : gates i,f,g
#define SH_OFF_F    (SW_F4 * 4)           // 49152 : h, 8*128 floats
#define SEXIF_OFF_F (SH_OFF_F + ROWS * HID)       // 50176 : float2[4][128] i,f rows 4-7
#define SEXGO_OFF_F (SEXIF_OFF_F + 4 * HID * 2)   // 51200 : float2[4][128] g,o rows 0-3
#define SWOUT_OFF_F (SEXGO_OFF_F + 4 * HID * 2)   // 52224 : float4[7][33]
#define SMEM_BYTES  ((SWOUT_OFF_F + OUT_DIM * 33 * 4) * 4)   // 212592

__global__ void __launch_bounds__(TPB, 1)
lstm_kernel(const float* __restrict__ ctx,
            const float* __restrict__ Wout,
            const float* __restrict__ bout,
            float* __restrict__ out) {
    extern __shared__ float smem[];
    float4* s_w    = reinterpret_cast<float4*>(smem);
    float*  s_h    = smem + SH_OFF_F;
    float2* s_exIF = reinterpret_cast<float2*>(smem + SEXIF_OFF_F);
    float2* s_exGO = reinterpret_cast<float2*>(smem + SEXGO_OFF_F);
    float4* s_wout = reinterpret_cast<float4*>(smem + SWOUT_OFF_F);

    const int t   = threadIdx.x;
    const int u   = t & (HID - 1);     // hidden unit
    const int hi  = t >> 7;            // 0: gates i,f / rows 0-3 ; 1: gates g,o / rows 4-7
    const int blk = blockIdx.x;

    // stage W (i,f,g) into shared
    for (int i = t; i < SW_F4; i += TPB) {
        int k4 = i / 384;
        int g  = i - k4 * 384;
        s_w[i] = g_W[k4 * GATES + g];
    }
    // stage W_out (padded pitch 33)
    const float4* Wout4 = reinterpret_cast<const float4*>(Wout);
    for (int i = t; i < OUT_DIM * 32; i += TPB) {
        int o = i / 32, kk = i - o * 32;
        s_wout[o * 33 + kk] = Wout4[o * 32 + kk];
    }
    // h0 = ctx[b][255][:]
    for (int i = t; i < ROWS * HID; i += TPB) {
        int r = i >> 7, col = i & (HID - 1);
        int b = blk * ROWS + r;
        s_h[i] = ctx[((size_t)b * 256 + 255) * HID + col];
    }

    // per-thread biases: hi=0 -> (i,f) of unit u ; hi=1 -> (g,o)
    const float bA = g_bias[hi * 2 * HID + u];
    const float bB = g_bias[hi * 2 * HID + HID + u];

    // o-gate L2 stream base (used by hi=1 only)
    const ulonglong2* __restrict__ wO =
        reinterpret_cast<const ulonglong2*>(&g_W[3 * HID + u]);

    // pred mapping: each warp owns one batch row, 7 active lanes
    const int pr = t >> 5;             // row 0..7
    const int po = t & 31;             // active if < 7
    const float bpred = (po < OUT_DIM) ? bout[po] : 0.0f;
    float* out_base = out + ((size_t)(blk * ROWS + pr) * T_STEPS) * OUT_DIM + po;

    float c[4];
#pragma unroll
    for (int r = 0; r < 4; r++) c[r] = 0.0f;

    __syncthreads();

    for (int s = 0; s < T_STEPS; s++) {
        unsigned long long aA[ROWS], aB[ROWS];
#pragma unroll
        for (int r = 0; r < ROWS; r++) { aA[r] = 0ull; aB[r] = 0ull; }

        if (hi == 0) {
            // gates i, f — both from SMEM
#pragma unroll 4
            for (int k4 = 0; k4 < 32; k4++) {
                ulonglong2 w0 = *reinterpret_cast<const ulonglong2*>(&s_w[k4 * 384 + u]);
                ulonglong2 w1 = *reinterpret_cast<const ulonglong2*>(&s_w[k4 * 384 + HID + u]);
#pragma unroll
                for (int r = 0; r < ROWS; r++) {
                    ulonglong2 h2 = *reinterpret_cast<const ulonglong2*>(s_h + r * HID + k4 * 4);
                    ffma2(aA[r], h2.x, w0.x); ffma2(aA[r], h2.y, w0.y);
                    ffma2(aB[r], h2.x, w1.x); ffma2(aB[r], h2.y, w1.y);
                }
            }
        } else {
            // gate g from SMEM, gate o streamed from L2 (4-ahead prefetch)
            ulonglong2 w3buf[4];
#pragma unroll
            for (int j = 0; j < 4; j++) w3buf[j] = __ldg(&wO[(size_t)j * GATES]);
#pragma unroll 4
            for (int k4 = 0; k4 < 32; k4++) {
                ulonglong2 w0 = *reinterpret_cast<const ulonglong2*>(&s_w[k4 * 384 + 2 * HID + u]);
                ulonglong2 w1 = w3buf[k4 & 3];
                if ((k4 & 3) == 3 && k4 + 1 < 32) {
#pragma unroll
                    for (int j = 0; j < 4; j++)
                        w3buf[j] = __ldg(&wO[(size_t)(k4 + 1 + j) * GATES]);
                }
#pragma unroll
                for (int r = 0; r < ROWS; r++) {
                    ulonglong2 h2 = *reinterpret_cast<const ulonglong2*>(s_h + r * HID + k4 * 4);
                    ffma2(aA[r], h2.x, w0.x); ffma2(aA[r], h2.y, w0.y);
                    ffma2(aB[r], h2.x, w1.x); ffma2(aB[r], h2.y, w1.y);
                }
            }
        }

        // biased gate values
        float gA[ROWS], gB[ROWS];
#pragma unroll
        for (int r = 0; r < ROWS; r++) {
            gA[r] = pairsum(aA[r]) + bA;
            gB[r] = pairsum(aB[r]) + bB;
        }

        // exchange the halves the partner needs
        if (hi == 0) {
#pragma unroll
            for (int r = 0; r < 4; r++)
                s_exIF[r * HID + u] = make_float2(gA[r + 4], gB[r + 4]);   // i,f rows 4-7
        } else {
#pragma unroll
            for (int r = 0; r < 4; r++)
                s_exGO[r * HID + u] = make_float2(gA[r], gB[r]);           // g,o rows 0-3
        }
        __syncthreads();

        // elementwise: low thread rows 0-3, high thread rows 4-7
        if (hi == 0) {
#pragma unroll
            for (int r = 0; r < 4; r++) {
                float2 go = s_exGO[r * HID + u];
                float iv = sigf(gA[r]);
                float fv = sigf(gB[r]);
                float gv = tanh_fast(go.x);
                float ov = sigf(go.y);
                c[r] = fv * c[r] + iv * gv;
                s_h[r * HID + u] = ov * tanh_fast(c[r]);
            }
        } else {
#pragma unroll
            for (int r = 0; r < 4; r++) {
                float2 iff = s_exIF[r * HID + u];
                float iv = sigf(iff.x);
                float fv = sigf(iff.y);
                float gv = tanh_fast(gA[r + 4]);
                float ov = sigf(gB[r + 4]);
                c[r] = fv * c[r] + iv * gv;
                s_h[(r + 4) * HID + u] = ov * tanh_fast(c[r]);
            }
        }
        __syncthreads();

        // pred = h_new @ W_out^T + b_out  (7 lanes per warp; overlaps next GEMM)
        if (po < OUT_DIM) {
            const float4* hr = reinterpret_cast<const float4*>(s_h + pr * HID);
            const float4* wr = s_wout + po * 33;
            float pa = 0.0f;
#pragma unroll 8
            for (int kk = 0; kk < 32; kk++) {
                float4 hv = hr[kk];
                float4 wv = wr[kk];
                pa += hv.x * wv.x + hv.y * wv.y + hv.z * wv.z + hv.w * wv.w;
            }
            out_base[(size_t)s * OUT_DIM] = pa + bpred;
        }
    }
}

extern "C" void kernel_launch(void* const* d_in, const int* in_sizes, int n_in,
                              void* d_out, int out_size) {
    const float* ctx  = (const float*)d_in[0];
    const float* Wih  = (const float*)d_in[1];
    const float* Whh  = (const float*)d_in[2];
    const float* bih  = (const float*)d_in[3];
    const float* bhh  = (const float*)d_in[4];
    const float* Wout = (const float*)d_in[5];
    const float* bout = (const float*)d_in[6];
    float* out = (float*)d_out;

    cudaFuncSetAttribute(lstm_kernel, cudaFuncAttributeMaxDynamicSharedMemorySize, SMEM_BYTES);

    prep_kernel<<<64, 256>>>(Wih, Whh, bih, bhh);
    lstm_kernel<<<NBLOCKS, TPB, SMEM_BYTES>>>(ctx, Wout, bout, out);
}

// round 6
// speedup vs baseline: 1.1019x; 1.1019x over previous
#include <cuda_runtime.h>
#include <cuda_bf16.h>
#include <cstdint>

// LSTM decoder: B=1024, H=128, O=7, T=512.
// gates = h @ (W_ih+W_hh)^T + (b_ih+b_hh)
// 128 blocks x 256 threads (2 warps/SMSP). ROW-split: thread (t) owns hidden
// unit u = t&127, ALL 4 gates, for 4 batch rows (group hi = t>>7 -> rows
// hi*4..hi*4+3). Elementwise fully thread-local, double-buffered h,
// ONE sync per step. Inner products in packed fp32x2 (fma.rn.f32x2).
// Gates i,f,g weights in SMEM; o-gate streamed from L2 with 4-ahead prefetch.

#define B_TOTAL   1024
#define HID       128
#define GATES     512
#define T_STEPS   512
#define OUT_DIM   7
#define ROWS      8
#define RPT       4                  // rows per thread
#define NBLOCKS   (B_TOTAL / ROWS)   // 128
#define TPB       256

__device__ float4 g_W[32 * GATES];   // [k4][g] combined transposed weights, 256 KB
__device__ float  g_bias[GATES];

// ---------- helpers ----------
__device__ __forceinline__ void ffma2(unsigned long long& d,
                                      unsigned long long a,
                                      unsigned long long b) {
    asm("fma.rn.f32x2 %0, %1, %2, %0;" : "+l"(d) : "l"(a), "l"(b));
}
__device__ __forceinline__ unsigned long long pack_bias(float b) {
    unsigned long long v;
    asm("mov.b64 %0, {%1, %2};" : "=l"(v) : "f"(b), "f"(0.0f));
    return v;
}
__device__ __forceinline__ float pairsum(unsigned long long v) {
    float a, b;
    asm("mov.b64 {%0, %1}, %2;" : "=f"(a), "=f"(b) : "l"(v));
    return a + b;
}
__device__ __forceinline__ float sigf(float x) {
    return __fdividef(1.0f, 1.0f + __expf(-x));
}
__device__ __forceinline__ float tanh_fast(float x) {
    return __fdividef(2.0f, 1.0f + __expf(-2.0f * x)) - 1.0f;
}

// ---------- prep ----------
__global__ void prep_kernel(const float* __restrict__ Wih,
                            const float* __restrict__ Whh,
                            const float* __restrict__ bih,
                            const float* __restrict__ bhh) {
    int idx = blockIdx.x * blockDim.x + threadIdx.x;
    if (idx < 32 * GATES) {
        int g  = idx & (GATES - 1);
        int k4 = idx >> 9;
        int base = g * HID + k4 * 4;
        float4 v;
        v.x = Wih[base + 0] + Whh[base + 0];
        v.y = Wih[base + 1] + Whh[base + 1];
        v.z = Wih[base + 2] + Whh[base + 2];
        v.w = Wih[base + 3] + Whh[base + 3];
        g_W[k4 * GATES + g] = v;
    }
    if (idx < GATES) g_bias[idx] = bih[idx] + bhh[idx];
}

// ---------- SMEM layout (floats) ----------
#define SW_F4       (32 * 384)                 // 12288 float4 : gates i,f,g
#define SH_OFF_F    (SW_F4 * 4)                // 49152 : h double buffer 2*8*128
#define SWOUT_OFF_F (SH_OFF_F + 2 * ROWS * HID)  // 51200 : float4[7][33]
#define SMEM_BYTES  ((SWOUT_OFF_F + OUT_DIM * 33 * 4) * 4)   // 208496

__global__ void __launch_bounds__(TPB, 1)
lstm_kernel(const float* __restrict__ ctx,
            const float* __restrict__ Wout,
            const float* __restrict__ bout,
            float* __restrict__ out) {
    extern __shared__ float smem[];
    float4* s_w    = reinterpret_cast<float4*>(smem);
    float*  s_h    = smem + SH_OFF_F;
    float4* s_wout = reinterpret_cast<float4*>(smem + SWOUT_OFF_F);

    const int t   = threadIdx.x;
    const int u   = t & (HID - 1);     // hidden unit
    const int hi  = t >> 7;            // row group: rows hi*4 .. hi*4+3
    const int rb  = hi * RPT;          // row base
    const int blk = blockIdx.x;

    // stage W (i,f,g) into shared
    for (int i = t; i < SW_F4; i += TPB) {
        int k4 = i / 384;
        int g  = i - k4 * 384;
        s_w[i] = g_W[k4 * GATES + g];
    }
    // stage W_out (padded pitch 33)
    const float4* Wout4 = reinterpret_cast<const float4*>(Wout);
    for (int i = t; i < OUT_DIM * 32; i += TPB) {
        int o = i / 32, kk = i - o * 32;
        s_wout[o * 33 + kk] = Wout4[o * 32 + kk];
    }
    // h0 = ctx[b][255][:]
    for (int i = t; i < ROWS * HID; i += TPB) {
        int r = i >> 7, col = i & (HID - 1);
        int b = blk * ROWS + r;
        s_h[i] = ctx[((size_t)b * 256 + 255) * HID + col];
    }

    // biases of unit u's 4 gates, packed for accumulator init
    const unsigned long long bi = pack_bias(g_bias[u]);
    const unsigned long long bf = pack_bias(g_bias[HID + u]);
    const unsigned long long bg = pack_bias(g_bias[2 * HID + u]);
    const unsigned long long bo = pack_bias(g_bias[3 * HID + u]);

    // o-gate L2 stream base
    const ulonglong2* __restrict__ wO =
        reinterpret_cast<const ulonglong2*>(&g_W[3 * HID + u]);

    // pred mapping: each of the 8 warps owns one batch row, 7 active lanes
    const int pr = t >> 5;             // row 0..7
    const int po = t & 31;             // active if < 7
    const float bpred = (po < OUT_DIM) ? bout[po] : 0.0f;
    float* out_base = out + ((size_t)(blk * ROWS + pr) * T_STEPS) * OUT_DIM + po;

    float c[RPT];
#pragma unroll
    for (int r = 0; r < RPT; r++) c[r] = 0.0f;

    __syncthreads();

    int cur = 0;
    for (int s = 0; s < T_STEPS; s++) {
        const float* hc = s_h + cur * (ROWS * HID) + rb * HID;   // this thread's 4 rows
        float*       hn = s_h + (cur ^ 1) * (ROWS * HID);

        unsigned long long a0[RPT], a1[RPT], a2[RPT], a3[RPT];
#pragma unroll
        for (int r = 0; r < RPT; r++) { a0[r] = bi; a1[r] = bf; a2[r] = bg; a3[r] = bo; }

        // o-gate prefetch pipeline: group of 4 k4-rows ahead
        ulonglong2 w3buf[4];
#pragma unroll
        for (int j = 0; j < 4; j++) w3buf[j] = __ldg(&wO[(size_t)j * GATES]);

#pragma unroll 4
        for (int k4 = 0; k4 < 32; k4++) {
            ulonglong2 w0 = *reinterpret_cast<const ulonglong2*>(&s_w[k4 * 384 + u]);
            ulonglong2 w1 = *reinterpret_cast<const ulonglong2*>(&s_w[k4 * 384 + HID + u]);
            ulonglong2 w2 = *reinterpret_cast<const ulonglong2*>(&s_w[k4 * 384 + 2 * HID + u]);
            ulonglong2 w3 = w3buf[k4 & 3];
            if ((k4 & 3) == 3 && k4 + 1 < 32) {
#pragma unroll
                for (int j = 0; j < 4; j++)
                    w3buf[j] = __ldg(&wO[(size_t)(k4 + 1 + j) * GATES]);
            }
#pragma unroll
            for (int r = 0; r < RPT; r++) {
                ulonglong2 h2 = *reinterpret_cast<const ulonglong2*>(hc + r * HID + k4 * 4);
                ffma2(a0[r], h2.x, w0.x); ffma2(a0[r], h2.y, w0.y);
                ffma2(a1[r], h2.x, w1.x); ffma2(a1[r], h2.y, w1.y);
                ffma2(a2[r], h2.x, w2.x); ffma2(a2[r], h2.y, w2.y);
                ffma2(a3[r], h2.x, w3.x); ffma2(a3[r], h2.y, w3.y);
            }
        }

        // LSTM elementwise — fully thread-local (4 rows)
#pragma unroll
        for (int r = 0; r < RPT; r++) {
            float gi = pairsum(a0[r]);
            float gf = pairsum(a1[r]);
            float gg = pairsum(a2[r]);
            float go = pairsum(a3[r]);
            float iv = sigf(gi);
            float fv = sigf(gf);
            float gv = tanh_fast(gg);
            float ov = sigf(go);
            c[r] = fv * c[r] + iv * gv;
            hn[(rb + r) * HID + u] = ov * tanh_fast(c[r]);
        }
        __syncthreads();

        // pred = h_new @ W_out^T + b_out  (7 lanes per warp; overlaps next GEMM)
        if (po < OUT_DIM) {
            const float4* hr = reinterpret_cast<const float4*>(hn + pr * HID);
            const float4* wr = s_wout + po * 33;
            float pa = 0.0f;
#pragma unroll 8
            for (int kk = 0; kk < 32; kk++) {
                float4 hv = hr[kk];
                float4 wv = wr[kk];
                pa += hv.x * wv.x + hv.y * wv.y + hv.z * wv.z + hv.w * wv.w;
            }
            out_base[(size_t)s * OUT_DIM] = pa + bpred;
        }
        cur ^= 1;
    }
}

extern "C" void kernel_launch(void* const* d_in, const int* in_sizes, int n_in,
                              void* d_out, int out_size) {
    const float* ctx  = (const float*)d_in[0];
    const float* Wih  = (const float*)d_in[1];
    const float* Whh  = (const float*)d_in[2];
    const float* bih  = (const float*)d_in[3];
    const float* bhh  = (const float*)d_in[4];
    const float* Wout = (const float*)d_in[5];
    const float* bout = (const float*)d_in[6];
    float* out = (float*)d_out;

    cudaFuncSetAttribute(lstm_kernel, cudaFuncAttributeMaxDynamicSharedMemorySize, SMEM_BYTES);

    prep_kernel<<<64, 256>>>(Wih, Whh, bih, bhh);
    lstm_kernel<<<NBLOCKS, TPB, SMEM_BYTES>>>(ctx, Wout, bout, out);
}

// round 7
// speedup vs baseline: 1.1184x; 1.0149x over previous
#include <cuda_runtime.h>
#include <cuda_bf16.h>
#include <cstdint>

// LSTM decoder: B=1024, H=128, O=7, T=512.
// gates = h @ (W_ih+W_hh)^T + (b_ih+b_hh)
// 128 blocks x 256 threads (2 warps/SMSP). Interleaved row-split: lane l of
// warp w owns unit u = 16w + (l&15), row group hi = l>>4 (rows hi*4..hi*4+3).
// Both lane-halves read the SAME weight addresses -> crossbar broadcast dedup
// (weight LDS cost halved vs naive TPB=256). h padded to pitch 132 floats so
// the two half-warp h-broadcasts hit disjoint banks (1 wavefront).
// All 4 gates per thread, elementwise thread-local, double-buffered h,
// ONE sync per step. Inner products in packed fp32x2 (fma.rn.f32x2).
// Gates i,f,g weights in SMEM; o-gate streamed from L2 with 4-ahead prefetch.

#define B_TOTAL   1024
#define HID       128
#define GATES     512
#define T_STEPS   512
#define OUT_DIM   7
#define ROWS      8
#define RPT       4                  // rows per thread
#define HP        132                // h row pitch in floats (bank-skewed, 16B-aligned)
#define NBLOCKS   (B_TOTAL / ROWS)   // 128
#define TPB       256

__device__ float4 g_W[32 * GATES];   // [k4][g] combined transposed weights, 256 KB
__device__ float  g_bias[GATES];

// ---------- helpers ----------
__device__ __forceinline__ void ffma2(unsigned long long& d,
                                      unsigned long long a,
                                      unsigned long long b) {
    asm("fma.rn.f32x2 %0, %1, %2, %0;" : "+l"(d) : "l"(a), "l"(b));
}
__device__ __forceinline__ unsigned long long pack_bias(float b) {
    unsigned long long v;
    asm("mov.b64 %0, {%1, %2};" : "=l"(v) : "f"(b), "f"(0.0f));
    return v;
}
__device__ __forceinline__ float pairsum(unsigned long long v) {
    float a, b;
    asm("mov.b64 {%0, %1}, %2;" : "=f"(a), "=f"(b) : "l"(v));
    return a + b;
}
__device__ __forceinline__ float sigf(float x) {
    return __fdividef(1.0f, 1.0f + __expf(-x));
}
__device__ __forceinline__ float tanh_fast(float x) {
    return __fdividef(2.0f, 1.0f + __expf(-2.0f * x)) - 1.0f;
}

// ---------- prep ----------
__global__ void prep_kernel(const float* __restrict__ Wih,
                            const float* __restrict__ Whh,
                            const float* __restrict__ bih,
                            const float* __restrict__ bhh) {
    int idx = blockIdx.x * blockDim.x + threadIdx.x;
    if (idx < 32 * GATES) {
        int g  = idx & (GATES - 1);
        int k4 = idx >> 9;
        int base = g * HID + k4 * 4;
        float4 v;
        v.x = Wih[base + 0] + Whh[base + 0];
        v.y = Wih[base + 1] + Whh[base + 1];
        v.z = Wih[base + 2] + Whh[base + 2];
        v.w = Wih[base + 3] + Whh[base + 3];
        g_W[k4 * GATES + g] = v;
    }
    if (idx < GATES) g_bias[idx] = bih[idx] + bhh[idx];
}

// ---------- SMEM layout (floats) ----------
#define SW_F4       (32 * 384)                    // 12288 float4 : gates i,f,g
#define SH_OFF_F    (SW_F4 * 4)                   // 49152 : h double buffer 2*8*HP
#define SWOUT_OFF_F (SH_OFF_F + 2 * ROWS * HP)    // 49152 + 2112 = 51264
#define SMEM_BYTES  ((SWOUT_OFF_F + OUT_DIM * 33 * 4) * 4)   // 208752

__global__ void __launch_bounds__(TPB, 1)
lstm_kernel(const float* __restrict__ ctx,
            const float* __restrict__ Wout,
            const float* __restrict__ bout,
            float* __restrict__ out) {
    extern __shared__ float smem[];
    float4* s_w    = reinterpret_cast<float4*>(smem);
    float*  s_h    = smem + SH_OFF_F;
    float4* s_wout = reinterpret_cast<float4*>(smem + SWOUT_OFF_F);

    const int t   = threadIdx.x;
    const int u   = ((t >> 5) << 4) + (t & 15);   // unit: 16*warp + (lane&15)
    const int hi  = (t >> 4) & 1;                 // lane half -> row group
    const int rb  = hi * RPT;                     // row base
    const int blk = blockIdx.x;

    // stage W (i,f,g) into shared
    for (int i = t; i < SW_F4; i += TPB) {
        int k4 = i / 384;
        int g  = i - k4 * 384;
        s_w[i] = g_W[k4 * GATES + g];
    }
    // stage W_out (padded pitch 33)
    const float4* Wout4 = reinterpret_cast<const float4*>(Wout);
    for (int i = t; i < OUT_DIM * 32; i += TPB) {
        int o = i / 32, kk = i - o * 32;
        s_wout[o * 33 + kk] = Wout4[o * 32 + kk];
    }
    // h0 = ctx[b][255][:]  (into padded-pitch buffer 0)
    for (int i = t; i < ROWS * HID; i += TPB) {
        int r = i >> 7, col = i & (HID - 1);
        int b = blk * ROWS + r;
        s_h[r * HP + col] = ctx[((size_t)b * 256 + 255) * HID + col];
    }

    // biases of unit u's 4 gates, packed for accumulator init
    const unsigned long long bi = pack_bias(g_bias[u]);
    const unsigned long long bf = pack_bias(g_bias[HID + u]);
    const unsigned long long bg = pack_bias(g_bias[2 * HID + u]);
    const unsigned long long bo = pack_bias(g_bias[3 * HID + u]);

    // o-gate L2 stream base
    const ulonglong2* __restrict__ wO =
        reinterpret_cast<const ulonglong2*>(&g_W[3 * HID + u]);

    // pred mapping: each of the 8 warps owns one batch row, 7 active lanes
    const int pr = t >> 5;             // row 0..7 (warp id)
    const int po = t & 31;             // active if < 7
    const float bpred = (po < OUT_DIM) ? bout[po] : 0.0f;
    float* out_base = out + ((size_t)(blk * ROWS + pr) * T_STEPS) * OUT_DIM + po;

    float c[RPT];
#pragma unroll
    for (int r = 0; r < RPT; r++) c[r] = 0.0f;

    __syncthreads();

    int cur = 0;
    for (int s = 0; s < T_STEPS; s++) {
        const float* hc = s_h + cur * (ROWS * HP) + rb * HP;   // this thread's 4 rows
        float*       hn = s_h + (cur ^ 1) * (ROWS * HP);

        unsigned long long a0[RPT], a1[RPT], a2[RPT], a3[RPT];
#pragma unroll
        for (int r = 0; r < RPT; r++) { a0[r] = bi; a1[r] = bf; a2[r] = bg; a3[r] = bo; }

        // o-gate prefetch pipeline: group of 4 k4-rows ahead
        ulonglong2 w3buf[4];
#pragma unroll
        for (int j = 0; j < 4; j++) w3buf[j] = __ldg(&wO[(size_t)j * GATES]);

#pragma unroll 4
        for (int k4 = 0; k4 < 32; k4++) {
            ulonglong2 w0 = *reinterpret_cast<const ulonglong2*>(&s_w[k4 * 384 + u]);
            ulonglong2 w1 = *reinterpret_cast<const ulonglong2*>(&s_w[k4 * 384 + HID + u]);
            ulonglong2 w2 = *reinterpret_cast<const ulonglong2*>(&s_w[k4 * 384 + 2 * HID + u]);
            ulonglong2 w3 = w3buf[k4 & 3];
            if ((k4 & 3) == 3 && k4 + 1 < 32) {
#pragma unroll
                for (int j = 0; j < 4; j++)
                    w3buf[j] = __ldg(&wO[(size_t)(k4 + 1 + j) * GATES]);
            }
#pragma unroll
            for (int r = 0; r < RPT; r++) {
                ulonglong2 h2 = *reinterpret_cast<const ulonglong2*>(hc + r * HP + k4 * 4);
                ffma2(a0[r], h2.x, w0.x); ffma2(a0[r], h2.y, w0.y);
                ffma2(a1[r], h2.x, w1.x); ffma2(a1[r], h2.y, w1.y);
                ffma2(a2[r], h2.x, w2.x); ffma2(a2[r], h2.y, w2.y);
                ffma2(a3[r], h2.x, w3.x); ffma2(a3[r], h2.y, w3.y);
            }
        }

        // LSTM elementwise — fully thread-local (4 rows)
#pragma unroll
        for (int r = 0; r < RPT; r++) {
            float gi = pairsum(a0[r]);
            float gf = pairsum(a1[r]);
            float gg = pairsum(a2[r]);
            float go = pairsum(a3[r]);
            float iv = sigf(gi);
            float fv = sigf(gf);
            float gv = tanh_fast(gg);
            float ov = sigf(go);
            c[r] = fv * c[r] + iv * gv;
            hn[(rb + r) * HP + u] = ov * tanh_fast(c[r]);
        }
        __syncthreads();

        // pred = h_new @ W_out^T + b_out  (7 lanes per warp; overlaps next GEMM)
        if (po < OUT_DIM) {
            const float4* hr = reinterpret_cast<const float4*>(hn + pr * HP);
            const float4* wr = s_wout + po * 33;
            float pa = 0.0f;
#pragma unroll 8
            for (int kk = 0; kk < 32; kk++) {
                float4 hv = hr[kk];
                float4 wv = wr[kk];
                pa += hv.x * wv.x + hv.y * wv.y + hv.z * wv.z + hv.w * wv.w;
            }
            out_base[(size_t)s * OUT_DIM] = pa + bpred;
        }
        cur ^= 1;
    }
}

extern "C" void kernel_launch(void* const* d_in, const int* in_sizes, int n_in,
                              void* d_out, int out_size) {
    const float* ctx  = (const float*)d_in[0];
    const float* Wih  = (const float*)d_in[1];
    const float* Whh  = (const float*)d_in[2];
    const float* bih  = (const float*)d_in[3];
    const float* bhh  = (const float*)d_in[4];
    const float* Wout = (const float*)d_in[5];
    const float* bout = (const float*)d_in[6];
    float* out = (float*)d_out;

    cudaFuncSetAttribute(lstm_kernel, cudaFuncAttributeMaxDynamicSharedMemorySize, SMEM_BYTES);

    prep_kernel<<<64, 256>>>(Wih, Whh, bih, bhh);
    lstm_kernel<<<NBLOCKS, TPB, SMEM_BYTES>>>(ctx, Wout, bout, out);
}